// round 7
// baseline (speedup 1.0000x reference)
#include <cuda_runtime.h>
#include <cuda_bf16.h>
#include <cstdint>

// PIPNet fused gather + MLP via mma.sync (HMMA) bf16-split.
//   out[p] = relu(concat(g1[il[p]], g2[ir[p]]) @ W1^T + b1) @ W2^T + b2
// Per CTA: M=128 pairs, N=128 hidden, K=128.
// fp32 -> bf16 hi/lo; acc = hi*hi + lo*hi + hi*lo in fp32 (drop lo*lo).
// R6: fuse the 3 split-passes into ONE k-loop so each (A_hi,A_lo,B_hi,B_lo)
// fragment load feeds 48 MMAs instead of 16 -> 33% less LDSM traffic
// (we were L1/smem-bound at 81.7%), and far lower register pressure
// (R5 hit 255 regs / spills from the fully-unrolled 3-pass nest).

#define TILE 128
#define NTHREADS 256

// smem layout (bytes): 128x128 bf16 tiles, row stride 256B,
// 16B chunks xor-swizzled by (row&7) for conflict-free ldmatrix/STS.
#define SM_A_HI 0
#define SM_A_LO 32768
#define SM_B_HI 65536
#define SM_B_LO 98304
#define SM_B1   131072
#define SM_W2   131584
#define SM_RED  132096
#define SMEM_TOTAL (132096 + 1024 + 128)

static __device__ __forceinline__ uint32_t smem_u32(const void* p) {
    uint32_t a;
    asm("{ .reg .u64 t; cvta.to.shared.u64 t, %1; cvt.u32.u64 %0, t; }"
        : "=r"(a) : "l"(p));
    return a;
}

// Byte offset into a tile: row-major, 256B rows, swizzled 16B chunks.
static __device__ __forceinline__ uint32_t tile_off(int row, int chunk) {
    return (uint32_t)row * 256u + (uint32_t)((chunk ^ (row & 7)) * 16);
}

static __device__ __forceinline__ void ldsm_x4(uint32_t* r, uint32_t addr) {
    asm volatile("ldmatrix.sync.aligned.m8n8.x4.shared.b16 {%0,%1,%2,%3}, [%4];"
                 : "=r"(r[0]), "=r"(r[1]), "=r"(r[2]), "=r"(r[3]) : "r"(addr));
}
static __device__ __forceinline__ void mma_bf16(float* c, const uint32_t* a,
                                                uint32_t b0, uint32_t b1) {
    asm volatile("mma.sync.aligned.m16n8k16.row.col.f32.bf16.bf16.f32 "
                 "{%0,%1,%2,%3}, {%4,%5,%6,%7}, {%8,%9}, {%0,%1,%2,%3};"
                 : "+f"(c[0]), "+f"(c[1]), "+f"(c[2]), "+f"(c[3])
                 : "r"(a[0]), "r"(a[1]), "r"(a[2]), "r"(a[3]), "r"(b0), "r"(b1));
}

// Split 8 fp32 into bf16 hi and lo (residual) 16B vectors.
static __device__ __forceinline__ void split8(const float* src, uint4& hi, uint4& lo) {
    __nv_bfloat16 h[8], l[8];
    #pragma unroll
    for (int q = 0; q < 8; ++q) {
        float x = src[q];
        h[q] = __float2bfloat16_rn(x);
        l[q] = __float2bfloat16_rn(x - __bfloat162float(h[q]));
    }
    hi = *(const uint4*)h;
    lo = *(const uint4*)l;
}

__global__ __launch_bounds__(NTHREADS)
void pipnet_hmma_kernel(const float* __restrict__ g1,
                        const float* __restrict__ g2,
                        const int* __restrict__ idxL,
                        const int* __restrict__ idxR,
                        const float* __restrict__ W1,
                        const float* __restrict__ b1,
                        const float* __restrict__ W2,
                        const float* __restrict__ b2,
                        float* __restrict__ out,
                        int P, int Nnodes)
{
    extern __shared__ char smem[];
    const uint32_t sbase = smem_u32(smem);
    const int tid = threadIdx.x;
    const int wid = tid >> 5;
    const int lid = tid & 31;
    const long long base = (long long)blockIdx.x * TILE;

    // ---- Stage b1 / W2 ----
    if (tid < 128) {
        *(float*)(smem + SM_B1 + tid * 4) = b1[tid];
        *(float*)(smem + SM_W2 + tid * 4) = W2[tid];
    }

    // ---- Gather X rows, split hi/lo, store swizzled ----
    {
        int r = tid & 127;                 // tile row (pair)
        int h = tid >> 7;                  // 0: left/g1, 1: right/g2
        long long pair = base + r;
        if (pair >= P) pair = P - 1;
        int srcRow = h ? idxR[pair] : idxL[pair];
        if (srcRow < 0) srcRow = 0;
        if (srcRow >= Nnodes) srcRow = Nnodes - 1;
        const float* src = (h ? g2 : g1) + (long long)srcRow * 64;
        #pragma unroll
        for (int i = 0; i < 8; ++i) {      // 8 chunks of 8 cols in this half
            uint4 hi, lo;
            split8(src + i * 8, hi, lo);
            uint32_t off = tile_off(r, h * 8 + i);
            *(uint4*)(smem + SM_A_HI + off) = hi;
            *(uint4*)(smem + SM_A_LO + off) = lo;
        }
    }

    // ---- Stage W1 split (B[n][k] = W1[n][k]: k-contiguous = col-major KxN) ----
    #pragma unroll
    for (int it = 0; it < 8; ++it) {
        int t = tid + NTHREADS * it;       // 0..2047
        int row = t >> 4;                  // n
        int chunk = t & 15;                // 8-col chunk
        uint4 hi, lo;
        split8(W1 + row * 128 + chunk * 8, hi, lo);
        uint32_t off = tile_off(row, chunk);
        *(uint4*)(smem + SM_B_HI + off) = hi;
        *(uint4*)(smem + SM_B_LO + off) = lo;
    }
    __syncthreads();

    // ---- HMMA mainloop: warp = 32m x 64n; fused 3-term split per k-step ----
    const int m_base = (wid >> 1) * 32;
    const int nb = wid & 1;
    const int n_base = nb * 64;
    const int gl = lid & 7;
    const int grp = lid >> 3;

    float acc[2][8][4];
    #pragma unroll
    for (int a = 0; a < 2; ++a)
        #pragma unroll
        for (int c = 0; c < 8; ++c)
            #pragma unroll
            for (int q = 0; q < 4; ++q) acc[a][c][q] = 0.f;

    const uint32_t aHI = sbase + SM_A_HI;
    const uint32_t aLO = sbase + SM_A_LO;
    const uint32_t bHI = sbase + SM_B_HI;
    const uint32_t bLO = sbase + SM_B_LO;

    #pragma unroll
    for (int ks = 0; ks < 8; ++ks) {
        int kc = ks * 2;
        // A frags: hi and lo, 2 subtiles of 16 rows each
        uint32_t ahi[2][4], alo[2][4];
        #pragma unroll
        for (int mt = 0; mt < 2; ++mt) {
            int row = m_base + mt * 16 + (grp & 1) * 8 + gl;
            uint32_t off = tile_off(row, kc + (grp >> 1));
            ldsm_x4(ahi[mt], aHI + off);
            ldsm_x4(alo[mt], aLO + off);
        }
        // B frags: hi and lo; NON-trans x4 (W1 is k-contiguous per n-row)
        uint32_t bh0[8], bh1[8], bl0[8], bl1[8];
        #pragma unroll
        for (int pr = 0; pr < 4; ++pr) {
            int row = n_base + pr * 16 + (grp >> 1) * 8 + gl;
            uint32_t off = tile_off(row, kc + (grp & 1));
            uint32_t r[4];
            ldsm_x4(r, bHI + off);
            bh0[pr * 2] = r[0]; bh1[pr * 2] = r[1];
            bh0[pr * 2 + 1] = r[2]; bh1[pr * 2 + 1] = r[3];
            uint32_t s[4];
            ldsm_x4(s, bLO + off);
            bl0[pr * 2] = s[0]; bl1[pr * 2] = s[1];
            bl0[pr * 2 + 1] = s[2]; bl1[pr * 2 + 1] = s[3];
        }
        // 48 MMAs: hi*hi + lo*hi + hi*lo
        #pragma unroll
        for (int mt = 0; mt < 2; ++mt)
            #pragma unroll
            for (int c = 0; c < 8; ++c) {
                mma_bf16(acc[mt][c], ahi[mt], bh0[c], bh1[c]);
                mma_bf16(acc[mt][c], alo[mt], bh0[c], bh1[c]);
                mma_bf16(acc[mt][c], ahi[mt], bl0[c], bl1[c]);
            }
    }

    // ---- Epilogue: bias + ReLU + W2 dot from accumulators ----
    const float* s_b1 = (const float*)(smem + SM_B1);
    const float* s_w2 = (const float*)(smem + SM_W2);
    float* red = (float*)(smem + SM_RED);
    const int q2 = (lid & 3) * 2;

    float b1v[8][2], w2v[8][2];
    #pragma unroll
    for (int c = 0; c < 8; ++c) {
        int n = n_base + c * 8 + q2;
        b1v[c][0] = s_b1[n];     b1v[c][1] = s_b1[n + 1];
        w2v[c][0] = s_w2[n];     w2v[c][1] = s_w2[n + 1];
    }

    #pragma unroll
    for (int mt = 0; mt < 2; ++mt) {
        float pa = 0.f, pb = 0.f;   // rows (l>>2) and (l>>2)+8 of this 16-row tile
        #pragma unroll
        for (int c = 0; c < 8; ++c) {
            pa += fmaxf(acc[mt][c][0] + b1v[c][0], 0.f) * w2v[c][0]
                + fmaxf(acc[mt][c][1] + b1v[c][1], 0.f) * w2v[c][1];
            pb += fmaxf(acc[mt][c][2] + b1v[c][0], 0.f) * w2v[c][0]
                + fmaxf(acc[mt][c][3] + b1v[c][1], 0.f) * w2v[c][1];
        }
        pa += __shfl_xor_sync(0xffffffffu, pa, 1);
        pa += __shfl_xor_sync(0xffffffffu, pa, 2);
        pb += __shfl_xor_sync(0xffffffffu, pb, 1);
        pb += __shfl_xor_sync(0xffffffffu, pb, 2);
        if ((lid & 3) == 0) {
            int ra = m_base + mt * 16 + (lid >> 2);
            red[ra * 2 + nb] = pa;
            red[(ra + 8) * 2 + nb] = pb;
        }
    }
    __syncthreads();

    if (tid < 128) {
        float s = red[tid * 2] + red[tid * 2 + 1] + b2[0];
        long long p = base + tid;
        if (p < P) out[p] = s;
    }
}

extern "C" void kernel_launch(void* const* d_in, const int* in_sizes, int n_in,
                              void* d_out, int out_size) {
    const float* g1  = (const float*)d_in[0];   // graph1_x [N,64]
    const float* g2  = (const float*)d_in[1];   // graph2_x [N,64]
    const int*   il  = (const int*)d_in[2];     // idx_left  [P] int32
    const int*   ir  = (const int*)d_in[3];     // idx_right [P] int32
    const float* W1  = (const float*)d_in[4];   // [128,128]
    const float* b1  = (const float*)d_in[5];   // [128]
    const float* W2  = (const float*)d_in[6];   // [1,128]
    const float* b2  = (const float*)d_in[7];   // [1]
    float*       out = (float*)d_out;           // [P,1]

    int P = in_sizes[2];
    int Nnodes = in_sizes[0] / 64;
    int grid = (P + TILE - 1) / TILE;

    cudaFuncSetAttribute(pipnet_hmma_kernel,
                         cudaFuncAttributeMaxDynamicSharedMemorySize, SMEM_TOTAL);
    pipnet_hmma_kernel<<<grid, NTHREADS, SMEM_TOTAL>>>(
        g1, g2, il, ir, W1, b1, W2, b2, out, P, Nnodes);
}

// round 8
// speedup vs baseline: 1.3345x; 1.3345x over previous
#include <cuda_runtime.h>
#include <cuda_bf16.h>
#include <cstdint>

// PIPNet fused gather + MLP via mma.sync (HMMA) bf16-split.
//   out[p] = relu(concat(g1[il[p]], g2[ir[p]]) @ W1^T + b1) @ W2^T + b2
// Per CTA: M=128 pairs, N=128 hidden, K=128.
// fp32 -> bf16 hi/lo; acc = hi*hi + lo*hi + hi*lo in fp32 (drop lo*lo).
//
// R7: R5/R6 were latency-bound at 1 CTA/SM (gather and MMA phases serialized,
// no pipe saturated: occ 12%, issue 10%, tensor 19%, DRAM 6%). W1's mma
// fragments are CTA-invariant, so a prep kernel writes them (bf16-split,
// fragment-ordered) into a 64KB __device__ buffer; the mainloop fetches B via
// coalesced LDG.128 (L1/L2-resident). B leaves smem -> 67KB/CTA -> 2 CTAs/SM
// -> one CTA's random-gather latency hides under the other's MMA loop.

#define TILE 128
#define NTHREADS 256

// smem layout (bytes): A tiles only (row stride 256B, 16B chunks xor-swizzled).
#define SM_A_HI 0
#define SM_A_LO 32768
#define SM_B1   65536
#define SM_W2   66048
#define SM_RED  66560
#define SMEM_TOTAL (66560 + 1024 + 128)

// W1 fragment buffer: [nb(2)][ks(8)][pr(4)][h(2)][lane(32)][reg(4)] u32 = 64KB.
__device__ uint32_t g_Wfrag[2 * 8 * 4 * 2 * 32 * 4];

static __device__ __forceinline__ uint32_t smem_u32(const void* p) {
    uint32_t a;
    asm("{ .reg .u64 t; cvta.to.shared.u64 t, %1; cvt.u32.u64 %0, t; }"
        : "=r"(a) : "l"(p));
    return a;
}

static __device__ __forceinline__ uint32_t tile_off(int row, int chunk) {
    return (uint32_t)row * 256u + (uint32_t)((chunk ^ (row & 7)) * 16);
}

static __device__ __forceinline__ void ldsm_x4(uint32_t* r, uint32_t addr) {
    asm volatile("ldmatrix.sync.aligned.m8n8.x4.shared.b16 {%0,%1,%2,%3}, [%4];"
                 : "=r"(r[0]), "=r"(r[1]), "=r"(r[2]), "=r"(r[3]) : "r"(addr));
}
static __device__ __forceinline__ void mma_bf16(float* c, const uint32_t* a,
                                                uint32_t b0, uint32_t b1) {
    asm volatile("mma.sync.aligned.m16n8k16.row.col.f32.bf16.bf16.f32 "
                 "{%0,%1,%2,%3}, {%4,%5,%6,%7}, {%8,%9}, {%0,%1,%2,%3};"
                 : "+f"(c[0]), "+f"(c[1]), "+f"(c[2]), "+f"(c[3])
                 : "r"(a[0]), "r"(a[1]), "r"(a[2]), "r"(a[3]), "r"(b0), "r"(b1));
}

static __device__ __forceinline__ void split8(const float* src, uint4& hi, uint4& lo) {
    __nv_bfloat16 h[8], l[8];
    #pragma unroll
    for (int q = 0; q < 8; ++q) {
        float x = src[q];
        h[q] = __float2bfloat16_rn(x);
        l[q] = __float2bfloat16_rn(x - __bfloat162float(h[q]));
    }
    hi = *(const uint4*)h;
    lo = *(const uint4*)l;
}

// ---- Prep: write W1's bf16-split mma B-fragments in fragment order ----
// Fragment semantics (verified by the passing R5 kernel): for warp role nb,
// k-step ks, pair-row pr, NON-trans ldmatrix x4 reg j at lane l holds the
// b16x2 pair  W1h[n][k], W1h[n][k+1]  with
//   n = nb*64 + pr*16 + (j>>1)*8 + (l>>2),  k = ks*16 + (j&1)*8 + 2*(l&3).
__global__ void pipnet_prep_wfrag(const float* __restrict__ W1) {
    int flat = blockIdx.x * blockDim.x + threadIdx.x;   // 16384 entries
    if (flat >= 16384) return;
    int j  = flat & 3;
    int l  = (flat >> 2) & 31;
    int h  = (flat >> 7) & 1;
    int pr = (flat >> 8) & 3;
    int ks = (flat >> 10) & 7;
    int nb = (flat >> 13) & 1;
    int n = nb * 64 + pr * 16 + ((j >> 1) << 3) + (l >> 2);
    int k = ks * 16 + ((j & 1) << 3) + 2 * (l & 3);
    float x0 = W1[n * 128 + k];
    float x1 = W1[n * 128 + k + 1];
    __nv_bfloat16 h0 = __float2bfloat16_rn(x0);
    __nv_bfloat16 h1 = __float2bfloat16_rn(x1);
    __nv_bfloat16 v0, v1;
    if (h) {
        v0 = __float2bfloat16_rn(x0 - __bfloat162float(h0));
        v1 = __float2bfloat16_rn(x1 - __bfloat162float(h1));
    } else {
        v0 = h0; v1 = h1;
    }
    uint32_t w = (uint32_t)*(uint16_t*)&v0 | ((uint32_t)*(uint16_t*)&v1 << 16);
    g_Wfrag[flat] = w;
}

__global__ __launch_bounds__(NTHREADS, 2)
void pipnet_hmma_kernel(const float* __restrict__ g1,
                        const float* __restrict__ g2,
                        const int* __restrict__ idxL,
                        const int* __restrict__ idxR,
                        const float* __restrict__ b1,
                        const float* __restrict__ W2,
                        const float* __restrict__ b2,
                        float* __restrict__ out,
                        int P, int Nnodes)
{
    extern __shared__ char smem[];
    const uint32_t sbase = smem_u32(smem);
    const int tid = threadIdx.x;
    const int wid = tid >> 5;
    const int lid = tid & 31;
    const long long base = (long long)blockIdx.x * TILE;

    // ---- Stage b1 / W2 ----
    if (tid < 128) {
        *(float*)(smem + SM_B1 + tid * 4) = b1[tid];
        *(float*)(smem + SM_W2 + tid * 4) = W2[tid];
    }

    // ---- Gather X rows, split hi/lo, store swizzled ----
    {
        int r = tid & 127;                 // tile row (pair)
        int h = tid >> 7;                  // 0: left/g1, 1: right/g2
        long long pair = base + r;
        if (pair >= P) pair = P - 1;
        int srcRow = h ? idxR[pair] : idxL[pair];
        if (srcRow < 0) srcRow = 0;
        if (srcRow >= Nnodes) srcRow = Nnodes - 1;
        const float* src = (h ? g2 : g1) + (long long)srcRow * 64;
        #pragma unroll
        for (int i = 0; i < 8; ++i) {      // 8 chunks of 8 cols in this half
            uint4 hi, lo;
            split8(src + i * 8, hi, lo);
            uint32_t off = tile_off(r, h * 8 + i);
            *(uint4*)(smem + SM_A_HI + off) = hi;
            *(uint4*)(smem + SM_A_LO + off) = lo;
        }
    }
    __syncthreads();

    // ---- HMMA mainloop: warp = 32m x 64n; B frags via LDG from g_Wfrag ----
    const int m_base = (wid >> 1) * 32;
    const int nb = wid & 1;
    const int n_base = nb * 64;
    const int gl = lid & 7;
    const int grp = lid >> 3;

    float acc[2][8][4];
    #pragma unroll
    for (int a = 0; a < 2; ++a)
        #pragma unroll
        for (int c = 0; c < 8; ++c)
            #pragma unroll
            for (int q = 0; q < 4; ++q) acc[a][c][q] = 0.f;

    const uint32_t aHI = sbase + SM_A_HI;
    const uint32_t aLO = sbase + SM_A_LO;
    const uint4* __restrict__ Wf = (const uint4*)g_Wfrag;

    #pragma unroll
    for (int ks = 0; ks < 8; ++ks) {
        int kc = ks * 2;
        // A frags: hi and lo, 2 subtiles of 16 rows each (4 LDSM.x4)
        uint32_t ahi[2][4], alo[2][4];
        #pragma unroll
        for (int mt = 0; mt < 2; ++mt) {
            int row = m_base + mt * 16 + (grp & 1) * 8 + gl;
            uint32_t off = tile_off(row, kc + (grp >> 1));
            ldsm_x4(ahi[mt], aHI + off);
            ldsm_x4(alo[mt], aLO + off);
        }
        // B frags per half (pr pair) via coalesced LDG.128, then 24 MMAs
        const uint4* wk = Wf + ((nb * 8 + ks) * 4) * 64 + lid;  // + pr*64 + h*32
        #pragma unroll
        for (int half = 0; half < 2; ++half) {
            uint32_t bh0[4], bh1[4], bl0[4], bl1[4];
            #pragma unroll
            for (int q = 0; q < 2; ++q) {
                int pr = half * 2 + q;
                uint4 vh = wk[pr * 64];          // h = 0 (hi)
                uint4 vl = wk[pr * 64 + 32];     // h = 1 (lo)
                bh0[q * 2] = vh.x; bh1[q * 2] = vh.y;
                bh0[q * 2 + 1] = vh.z; bh1[q * 2 + 1] = vh.w;
                bl0[q * 2] = vl.x; bl1[q * 2] = vl.y;
                bl0[q * 2 + 1] = vl.z; bl1[q * 2 + 1] = vl.w;
            }
            #pragma unroll
            for (int mt = 0; mt < 2; ++mt)
                #pragma unroll
                for (int q = 0; q < 4; ++q) {
                    int c = half * 4 + q;
                    mma_bf16(acc[mt][c], ahi[mt], bh0[q], bh1[q]);
                    mma_bf16(acc[mt][c], alo[mt], bh0[q], bh1[q]);
                    mma_bf16(acc[mt][c], ahi[mt], bl0[q], bl1[q]);
                }
        }
    }

    // ---- Epilogue: bias + ReLU + W2 dot from accumulators ----
    const float* s_b1 = (const float*)(smem + SM_B1);
    const float* s_w2 = (const float*)(smem + SM_W2);
    float* red = (float*)(smem + SM_RED);
    const int q2 = (lid & 3) * 2;

    float b1v[8][2], w2v[8][2];
    #pragma unroll
    for (int c = 0; c < 8; ++c) {
        int n = n_base + c * 8 + q2;
        b1v[c][0] = s_b1[n];     b1v[c][1] = s_b1[n + 1];
        w2v[c][0] = s_w2[n];     w2v[c][1] = s_w2[n + 1];
    }

    #pragma unroll
    for (int mt = 0; mt < 2; ++mt) {
        float pa = 0.f, pb = 0.f;   // rows (l>>2) and (l>>2)+8 of this 16-row tile
        #pragma unroll
        for (int c = 0; c < 8; ++c) {
            pa += fmaxf(acc[mt][c][0] + b1v[c][0], 0.f) * w2v[c][0]
                + fmaxf(acc[mt][c][1] + b1v[c][1], 0.f) * w2v[c][1];
            pb += fmaxf(acc[mt][c][2] + b1v[c][0], 0.f) * w2v[c][0]
                + fmaxf(acc[mt][c][3] + b1v[c][1], 0.f) * w2v[c][1];
        }
        pa += __shfl_xor_sync(0xffffffffu, pa, 1);
        pa += __shfl_xor_sync(0xffffffffu, pa, 2);
        pb += __shfl_xor_sync(0xffffffffu, pb, 1);
        pb += __shfl_xor_sync(0xffffffffu, pb, 2);
        if ((lid & 3) == 0) {
            int ra = m_base + mt * 16 + (lid >> 2);
            red[ra * 2 + nb] = pa;
            red[(ra + 8) * 2 + nb] = pb;
        }
    }
    __syncthreads();

    if (tid < 128) {
        float s = red[tid * 2] + red[tid * 2 + 1] + b2[0];
        long long p = base + tid;
        if (p < P) out[p] = s;
    }
}

extern "C" void kernel_launch(void* const* d_in, const int* in_sizes, int n_in,
                              void* d_out, int out_size) {
    const float* g1  = (const float*)d_in[0];   // graph1_x [N,64]
    const float* g2  = (const float*)d_in[1];   // graph2_x [N,64]
    const int*   il  = (const int*)d_in[2];     // idx_left  [P] int32
    const int*   ir  = (const int*)d_in[3];     // idx_right [P] int32
    const float* W1  = (const float*)d_in[4];   // [128,128]
    const float* b1  = (const float*)d_in[5];   // [128]
    const float* W2  = (const float*)d_in[6];   // [1,128]
    const float* b2  = (const float*)d_in[7];   // [1]
    float*       out = (float*)d_out;           // [P,1]

    int P = in_sizes[2];
    int Nnodes = in_sizes[0] / 64;
    int grid = (P + TILE - 1) / TILE;

    pipnet_prep_wfrag<<<64, 256>>>(W1);

    cudaFuncSetAttribute(pipnet_hmma_kernel,
                         cudaFuncAttributeMaxDynamicSharedMemorySize, SMEM_TOTAL);
    pipnet_hmma_kernel<<<grid, NTHREADS, SMEM_TOTAL>>>(
        g1, g2, il, ir, b1, W2, b2, out, P, Nnodes);
}

// round 9
// speedup vs baseline: 4.3652x; 3.2710x over previous
#include <cuda_runtime.h>
#include <cuda_fp16.h>
#include <cstdint>

// PIPNet fused gather + MLP via mma.sync (HMMA) fp16 2-term split.
//   out[p] = relu(concat(g1[il[p]], g2[ir[p]]) @ W1^T + b1) @ W2^T + b2
// Per CTA: M=128 pairs, N=128 hidden, K=128.
//
// R8 (we are l1tex-wavefront bound, L1=86.6%):
//  - A split into fp16 hi+lo (residual exact to 2^-24); B = single fp16.
//    out = (Ahi+Alo)*Bfp16 drops only A*epsB (~2^-13) -> rel_err ~1e-4.
//    MMAs 48 -> 32 per k-step; B fragment traffic halved (32KB buffer).
//  - Coalesced gather: 16 lanes per node row (float4 each) -> warp touches
//    4 cache lines per request instead of 32.

#define TILE 128
#define NTHREADS 256

// smem layout (bytes): A tiles only (row stride 256B, 16B chunks xor-swizzled).
#define SM_A_HI 0
#define SM_A_LO 32768
#define SM_B1   65536
#define SM_W2   66048
#define SM_RED  66560
#define SMEM_TOTAL (66560 + 1024 + 128)

// W1 fp16 fragment buffer: [nb(2)][ks(8)][pr(4)][lane(32)][reg(4)] u32 = 32KB.
__device__ uint32_t g_Wfrag[2 * 8 * 4 * 32 * 4];

static __device__ __forceinline__ uint32_t smem_u32(const void* p) {
    uint32_t a;
    asm("{ .reg .u64 t; cvta.to.shared.u64 t, %1; cvt.u32.u64 %0, t; }"
        : "=r"(a) : "l"(p));
    return a;
}

static __device__ __forceinline__ uint32_t tile_off(int row, int chunk) {
    return (uint32_t)row * 256u + (uint32_t)((chunk ^ (row & 7)) * 16);
}

static __device__ __forceinline__ void ldsm_x4(uint32_t* r, uint32_t addr) {
    asm volatile("ldmatrix.sync.aligned.m8n8.x4.shared.b16 {%0,%1,%2,%3}, [%4];"
                 : "=r"(r[0]), "=r"(r[1]), "=r"(r[2]), "=r"(r[3]) : "r"(addr));
}
static __device__ __forceinline__ void mma_f16(float* c, const uint32_t* a,
                                               uint32_t b0, uint32_t b1) {
    asm volatile("mma.sync.aligned.m16n8k16.row.col.f32.f16.f16.f32 "
                 "{%0,%1,%2,%3}, {%4,%5,%6,%7}, {%8,%9}, {%0,%1,%2,%3};"
                 : "+f"(c[0]), "+f"(c[1]), "+f"(c[2]), "+f"(c[3])
                 : "r"(a[0]), "r"(a[1]), "r"(a[2]), "r"(a[3]), "r"(b0), "r"(b1));
}

static __device__ __forceinline__ uint32_t pack_h2(__half a, __half b) {
    __half2 h = __halves2half2(a, b);
    return *(uint32_t*)&h;
}

// ---- Prep: write W1's fp16 mma B-fragments in fragment order ----
// NON-trans ldmatrix x4 reg j at lane l holds the f16x2 pair
// W1h[n][k], W1h[n][k+1] with
//   n = nb*64 + pr*16 + (j>>1)*8 + (l>>2),  k = ks*16 + (j&1)*8 + 2*(l&3).
__global__ void pipnet_prep_wfrag(const float* __restrict__ W1) {
    int flat = blockIdx.x * blockDim.x + threadIdx.x;   // 8192 entries
    if (flat >= 8192) return;
    int j  = flat & 3;
    int l  = (flat >> 2) & 31;
    int pr = (flat >> 7) & 3;
    int ks = (flat >> 9) & 7;
    int nb = (flat >> 12) & 1;
    int n = nb * 64 + pr * 16 + ((j >> 1) << 3) + (l >> 2);
    int k = ks * 16 + ((j & 1) << 3) + 2 * (l & 3);
    g_Wfrag[flat] = pack_h2(__float2half_rn(W1[n * 128 + k]),
                            __float2half_rn(W1[n * 128 + k + 1]));
}

__global__ __launch_bounds__(NTHREADS, 2)
void pipnet_hmma_kernel(const float* __restrict__ g1,
                        const float* __restrict__ g2,
                        const int* __restrict__ idxL,
                        const int* __restrict__ idxR,
                        const float* __restrict__ b1,
                        const float* __restrict__ W2,
                        const float* __restrict__ b2,
                        float* __restrict__ out,
                        int P, int Nnodes)
{
    extern __shared__ char smem[];
    const uint32_t sbase = smem_u32(smem);
    const int tid = threadIdx.x;
    const int wid = tid >> 5;
    const int lid = tid & 31;
    const long long base = (long long)blockIdx.x * TILE;

    // ---- Stage b1 / W2 ----
    if (tid < 128) {
        *(float*)(smem + SM_B1 + tid * 4) = b1[tid];
        *(float*)(smem + SM_W2 + tid * 4) = W2[tid];
    }

    // ---- Coalesced gather: 16 lanes per node row, fp16 hi/lo split ----
    // Row-half rh in [0,256): r = rh & 127 (pair row), h = rh >> 7 (left/right).
    {
        const int lane_in = lid & 15;       // position within the row
        #pragma unroll
        for (int i = 0; i < 16; ++i) {
            int rh = wid * 32 + i * 2 + (lid >> 4);
            int r = rh & 127;
            int h = rh >> 7;
            long long pair = base + r;
            if (pair >= P) pair = P - 1;
            int srcRow = h ? idxR[pair] : idxL[pair];
            if (srcRow < 0) srcRow = 0;
            if (srcRow >= Nnodes) srcRow = Nnodes - 1;
            const float4* src =
                (const float4*)((h ? g2 : g1) + (long long)srcRow * 64);
            float4 v = src[lane_in];
            __half hx = __float2half_rn(v.x), hy = __float2half_rn(v.y);
            __half hz = __float2half_rn(v.z), hw = __float2half_rn(v.w);
            __half lx = __float2half_rn(v.x - __half2float(hx));
            __half ly = __float2half_rn(v.y - __half2float(hy));
            __half lz = __float2half_rn(v.z - __half2float(hz));
            __half lw = __float2half_rn(v.w - __half2float(hw));
            uint2 hi = make_uint2(pack_h2(hx, hy), pack_h2(hz, hw));
            uint2 lo = make_uint2(pack_h2(lx, ly), pack_h2(lz, lw));
            uint32_t off = tile_off(r, h * 8 + (lane_in >> 1)) + (lane_in & 1) * 8;
            *(uint2*)(smem + SM_A_HI + off) = hi;
            *(uint2*)(smem + SM_A_LO + off) = lo;
        }
    }
    __syncthreads();

    // ---- HMMA mainloop: warp = 32m x 64n; B frags via LDG from g_Wfrag ----
    const int m_base = (wid >> 1) * 32;
    const int nb = wid & 1;
    const int n_base = nb * 64;
    const int gl = lid & 7;
    const int grp = lid >> 3;

    float acc[2][8][4];
    #pragma unroll
    for (int a = 0; a < 2; ++a)
        #pragma unroll
        for (int c = 0; c < 8; ++c)
            #pragma unroll
            for (int q = 0; q < 4; ++q) acc[a][c][q] = 0.f;

    const uint32_t aHI = sbase + SM_A_HI;
    const uint32_t aLO = sbase + SM_A_LO;
    const uint4* __restrict__ Wf = (const uint4*)g_Wfrag;

    #pragma unroll
    for (int ks = 0; ks < 8; ++ks) {
        int kc = ks * 2;
        // A frags: hi and lo, 2 subtiles of 16 rows each (4 LDSM.x4)
        uint32_t ahi[2][4], alo[2][4];
        #pragma unroll
        for (int mt = 0; mt < 2; ++mt) {
            int row = m_base + mt * 16 + (grp & 1) * 8 + gl;
            uint32_t off = tile_off(row, kc + (grp >> 1));
            ldsm_x4(ahi[mt], aHI + off);
            ldsm_x4(alo[mt], aLO + off);
        }
        // B frags: 4 LDG.128 (one per pr), single fp16
        const uint4* wk = Wf + ((nb * 8 + ks) * 4) * 32 + lid;
        #pragma unroll
        for (int pr = 0; pr < 4; ++pr) {
            uint4 vb = wk[pr * 32];
            uint32_t b0a = vb.x, b1a = vb.y;   // n-chunk pr*2
            uint32_t b0b = vb.z, b1b = vb.w;   // n-chunk pr*2+1
            #pragma unroll
            for (int mt = 0; mt < 2; ++mt) {
                mma_f16(acc[mt][pr * 2],     ahi[mt], b0a, b1a);
                mma_f16(acc[mt][pr * 2],     alo[mt], b0a, b1a);
                mma_f16(acc[mt][pr * 2 + 1], ahi[mt], b0b, b1b);
                mma_f16(acc[mt][pr * 2 + 1], alo[mt], b0b, b1b);
            }
        }
    }

    // ---- Epilogue: bias + ReLU + W2 dot from accumulators ----
    const float* s_b1 = (const float*)(smem + SM_B1);
    const float* s_w2 = (const float*)(smem + SM_W2);
    float* red = (float*)(smem + SM_RED);
    const int q2 = (lid & 3) * 2;

    float b1v[8][2], w2v[8][2];
    #pragma unroll
    for (int c = 0; c < 8; ++c) {
        int n = n_base + c * 8 + q2;
        b1v[c][0] = s_b1[n];     b1v[c][1] = s_b1[n + 1];
        w2v[c][0] = s_w2[n];     w2v[c][1] = s_w2[n + 1];
    }

    #pragma unroll
    for (int mt = 0; mt < 2; ++mt) {
        float pa = 0.f, pb = 0.f;   // rows (l>>2) and (l>>2)+8 of this 16-row tile
        #pragma unroll
        for (int c = 0; c < 8; ++c) {
            pa += fmaxf(acc[mt][c][0] + b1v[c][0], 0.f) * w2v[c][0]
                + fmaxf(acc[mt][c][1] + b1v[c][1], 0.f) * w2v[c][1];
            pb += fmaxf(acc[mt][c][2] + b1v[c][0], 0.f) * w2v[c][0]
                + fmaxf(acc[mt][c][3] + b1v[c][1], 0.f) * w2v[c][1];
        }
        pa += __shfl_xor_sync(0xffffffffu, pa, 1);
        pa += __shfl_xor_sync(0xffffffffu, pa, 2);
        pb += __shfl_xor_sync(0xffffffffu, pb, 1);
        pb += __shfl_xor_sync(0xffffffffu, pb, 2);
        if ((lid & 3) == 0) {
            int ra = m_base + mt * 16 + (lid >> 2);
            red[ra * 2 + nb] = pa;
            red[(ra + 8) * 2 + nb] = pb;
        }
    }
    __syncthreads();

    if (tid < 128) {
        float s = red[tid * 2] + red[tid * 2 + 1] + b2[0];
        long long p = base + tid;
        if (p < P) out[p] = s;
    }
}

extern "C" void kernel_launch(void* const* d_in, const int* in_sizes, int n_in,
                              void* d_out, int out_size) {
    const float* g1  = (const float*)d_in[0];   // graph1_x [N,64]
    const float* g2  = (const float*)d_in[1];   // graph2_x [N,64]
    const int*   il  = (const int*)d_in[2];     // idx_left  [P] int32
    const int*   ir  = (const int*)d_in[3];     // idx_right [P] int32
    const float* W1  = (const float*)d_in[4];   // [128,128]
    const float* b1  = (const float*)d_in[5];   // [128]
    const float* W2  = (const float*)d_in[6];   // [1,128]
    const float* b2  = (const float*)d_in[7];   // [1]
    float*       out = (float*)d_out;           // [P,1]

    int P = in_sizes[2];
    int Nnodes = in_sizes[0] / 64;
    int grid = (P + TILE - 1) / TILE;

    pipnet_prep_wfrag<<<32, 256>>>(W1);

    cudaFuncSetAttribute(pipnet_hmma_kernel,
                         cudaFuncAttributeMaxDynamicSharedMemorySize, SMEM_TOTAL);
    pipnet_hmma_kernel<<<grid, NTHREADS, SMEM_TOTAL>>>(
        g1, g2, il, ir, b1, W2, b2, out, P, Nnodes);
}

// round 10
// speedup vs baseline: 4.8773x; 1.1173x over previous
#include <cuda_runtime.h>
#include <cuda_fp16.h>
#include <cstdint>

// PIPNet fused gather + MLP via mma.sync (HMMA) single-fp16.
//   out[p] = relu(concat(g1[il[p]], g2[ir[p]]) @ W1^T + b1) @ W2^T + b2
//
// R9: (a) drop the A-lo split term -- measured 2.5e-4 error was all from B's
// fp16 rounding; A fp16 adds the same magnitude -> ~3.5e-4 total, still 3x
// under threshold. Tensor work halves (floor ~54us). (b) M-tile 128->64:
// acc 64->32 regs, smem 67KB->18KB -> 3+ CTAs/SM to hide gather latency.

#define MTILE 64
#define NTHREADS 256

// smem layout (bytes): A tile 64x128 fp16, rows 256B, 16B chunks xor-swizzled.
#define SM_A    0
#define SM_B1   16384
#define SM_W2   16896
#define SM_RED  17408
#define SMEM_TOTAL (17408 + 512 + 128)

// W1 fp16 fragment buffer: [nb(2)][ks(8)][pr(4)][lane(32)][reg(4)] u32 = 32KB.
__device__ uint32_t g_Wfrag[2 * 8 * 4 * 32 * 4];

static __device__ __forceinline__ uint32_t smem_u32(const void* p) {
    uint32_t a;
    asm("{ .reg .u64 t; cvta.to.shared.u64 t, %1; cvt.u32.u64 %0, t; }"
        : "=r"(a) : "l"(p));
    return a;
}

static __device__ __forceinline__ uint32_t tile_off(int row, int chunk) {
    return (uint32_t)row * 256u + (uint32_t)((chunk ^ (row & 7)) * 16);
}

static __device__ __forceinline__ void ldsm_x4(uint32_t* r, uint32_t addr) {
    asm volatile("ldmatrix.sync.aligned.m8n8.x4.shared.b16 {%0,%1,%2,%3}, [%4];"
                 : "=r"(r[0]), "=r"(r[1]), "=r"(r[2]), "=r"(r[3]) : "r"(addr));
}
static __device__ __forceinline__ void mma_f16(float* c, const uint32_t* a,
                                               uint32_t b0, uint32_t b1) {
    asm volatile("mma.sync.aligned.m16n8k16.row.col.f32.f16.f16.f32 "
                 "{%0,%1,%2,%3}, {%4,%5,%6,%7}, {%8,%9}, {%0,%1,%2,%3};"
                 : "+f"(c[0]), "+f"(c[1]), "+f"(c[2]), "+f"(c[3])
                 : "r"(a[0]), "r"(a[1]), "r"(a[2]), "r"(a[3]), "r"(b0), "r"(b1));
}

static __device__ __forceinline__ uint32_t pack_h2(__half a, __half b) {
    __half2 h = __halves2half2(a, b);
    return *(uint32_t*)&h;
}

// ---- Prep: write W1's fp16 mma B-fragments in fragment order ----
// NON-trans ldmatrix x4 reg j at lane l holds the f16x2 pair
// W1h[n][k], W1h[n][k+1] with
//   n = nb*64 + pr*16 + (j>>1)*8 + (l>>2),  k = ks*16 + (j&1)*8 + 2*(l&3).
__global__ void pipnet_prep_wfrag(const float* __restrict__ W1) {
    int flat = blockIdx.x * blockDim.x + threadIdx.x;   // 8192 entries
    if (flat >= 8192) return;
    int j  = flat & 3;
    int l  = (flat >> 2) & 31;
    int pr = (flat >> 7) & 3;
    int ks = (flat >> 9) & 7;
    int nb = (flat >> 12) & 1;
    int n = nb * 64 + pr * 16 + ((j >> 1) << 3) + (l >> 2);
    int k = ks * 16 + ((j & 1) << 3) + 2 * (l & 3);
    g_Wfrag[flat] = pack_h2(__float2half_rn(W1[n * 128 + k]),
                            __float2half_rn(W1[n * 128 + k + 1]));
}

__global__ __launch_bounds__(NTHREADS, 3)
void pipnet_hmma_kernel(const float* __restrict__ g1,
                        const float* __restrict__ g2,
                        const int* __restrict__ idxL,
                        const int* __restrict__ idxR,
                        const float* __restrict__ b1,
                        const float* __restrict__ W2,
                        const float* __restrict__ b2,
                        float* __restrict__ out,
                        int P, int Nnodes)
{
    extern __shared__ char smem[];
    const uint32_t sbase = smem_u32(smem);
    const int tid = threadIdx.x;
    const int wid = tid >> 5;
    const int lid = tid & 31;
    const long long base = (long long)blockIdx.x * MTILE;

    // ---- Stage b1 / W2 ----
    if (tid < 128) {
        *(float*)(smem + SM_B1 + tid * 4) = b1[tid];
        *(float*)(smem + SM_W2 + tid * 4) = W2[tid];
    }

    // ---- Coalesced gather: 16 lanes per node row, single fp16 ----
    // 128 row-halves: rh in [0,128), r = rh & 63 (pair row), h = rh >> 6.
    {
        const int lane_in = lid & 15;       // float4 position within the row
        #pragma unroll
        for (int i = 0; i < 8; ++i) {
            int rh = wid * 16 + i * 2 + (lid >> 4);
            int r = rh & 63;
            int h = rh >> 6;
            long long pair = base + r;
            if (pair >= P) pair = P - 1;
            int srcRow = h ? idxR[pair] : idxL[pair];
            if (srcRow < 0) srcRow = 0;
            if (srcRow >= Nnodes) srcRow = Nnodes - 1;
            const float4* src =
                (const float4*)((h ? g2 : g1) + (long long)srcRow * 64);
            float4 v = src[lane_in];
            uint2 hv = make_uint2(pack_h2(__float2half_rn(v.x), __float2half_rn(v.y)),
                                  pack_h2(__float2half_rn(v.z), __float2half_rn(v.w)));
            uint32_t off = tile_off(r, h * 8 + (lane_in >> 1)) + (lane_in & 1) * 8;
            *(uint2*)(smem + SM_A + off) = hv;
        }
    }
    __syncthreads();

    // ---- HMMA mainloop: warp = 16m x 64n ----
    const int m_base = (wid >> 1) * 16;
    const int nb = wid & 1;
    const int n_base = nb * 64;
    const int gl = lid & 7;
    const int grp = lid >> 3;

    float acc[8][4];
    #pragma unroll
    for (int c = 0; c < 8; ++c)
        #pragma unroll
        for (int q = 0; q < 4; ++q) acc[c][q] = 0.f;

    const uint32_t aT = sbase + SM_A;
    const uint4* __restrict__ Wf = (const uint4*)g_Wfrag;

    #pragma unroll
    for (int ks = 0; ks < 8; ++ks) {
        int kc = ks * 2;
        // A frag: one LDSM.x4 covering 16 rows x 16 cols
        uint32_t af[4];
        {
            int row = m_base + (grp & 1) * 8 + gl;
            ldsm_x4(af, aT + tile_off(row, kc + (grp >> 1)));
        }
        // B frags: 4 LDG.128 (one per pr), 8 MMAs
        const uint4* wk = Wf + ((nb * 8 + ks) * 4) * 32 + lid;
        #pragma unroll
        for (int pr = 0; pr < 4; ++pr) {
            uint4 vb = wk[pr * 32];
            mma_f16(acc[pr * 2],     af, vb.x, vb.y);
            mma_f16(acc[pr * 2 + 1], af, vb.z, vb.w);
        }
    }

    // ---- Epilogue: bias + ReLU + W2 dot from accumulators ----
    const float* s_b1 = (const float*)(smem + SM_B1);
    const float* s_w2 = (const float*)(smem + SM_W2);
    float* red = (float*)(smem + SM_RED);
    const int q2 = (lid & 3) * 2;

    float pa = 0.f, pb = 0.f;   // rows m_base+(lid>>2) and +8
    #pragma unroll
    for (int c = 0; c < 8; ++c) {
        int n = n_base + c * 8 + q2;
        float b0 = s_b1[n], b1v = s_b1[n + 1];
        float w0 = s_w2[n], w1v = s_w2[n + 1];
        pa += fmaxf(acc[c][0] + b0, 0.f) * w0 + fmaxf(acc[c][1] + b1v, 0.f) * w1v;
        pb += fmaxf(acc[c][2] + b0, 0.f) * w0 + fmaxf(acc[c][3] + b1v, 0.f) * w1v;
    }
    pa += __shfl_xor_sync(0xffffffffu, pa, 1);
    pa += __shfl_xor_sync(0xffffffffu, pa, 2);
    pb += __shfl_xor_sync(0xffffffffu, pb, 1);
    pb += __shfl_xor_sync(0xffffffffu, pb, 2);
    if ((lid & 3) == 0) {
        int ra = m_base + (lid >> 2);
        red[ra * 2 + nb] = pa;
        red[(ra + 8) * 2 + nb] = pb;
    }
    __syncthreads();

    if (tid < MTILE) {
        float s = red[tid * 2] + red[tid * 2 + 1] + b2[0];
        long long p = base + tid;
        if (p < P) out[p] = s;
    }
}

extern "C" void kernel_launch(void* const* d_in, const int* in_sizes, int n_in,
                              void* d_out, int out_size) {
    const float* g1  = (const float*)d_in[0];   // graph1_x [N,64]
    const float* g2  = (const float*)d_in[1];   // graph2_x [N,64]
    const int*   il  = (const int*)d_in[2];     // idx_left  [P] int32
    const int*   ir  = (const int*)d_in[3];     // idx_right [P] int32
    const float* W1  = (const float*)d_in[4];   // [128,128]
    const float* b1  = (const float*)d_in[5];   // [128]
    const float* W2  = (const float*)d_in[6];   // [1,128]
    const float* b2  = (const float*)d_in[7];   // [1]
    float*       out = (float*)d_out;           // [P,1]

    int P = in_sizes[2];
    int Nnodes = in_sizes[0] / 64;
    int grid = (P + MTILE - 1) / MTILE;

    pipnet_prep_wfrag<<<32, 256>>>(W1);

    cudaFuncSetAttribute(pipnet_hmma_kernel,
                         cudaFuncAttributeMaxDynamicSharedMemorySize, SMEM_TOTAL);
    pipnet_hmma_kernel<<<grid, NTHREADS, SMEM_TOTAL>>>(
        g1, g2, il, ir, b1, W2, b2, out, P, Nnodes);
}